// round 14
// baseline (speedup 1.0000x reference)
#include <cuda_runtime.h>
#include <cuda_fp16.h>
#include <math.h>
#include <stdint.h>

// ---------------- problem constants ----------------
#define BTT   40
#define NTOK  199
#define DIMD  768
#define DEPTH 12
#define HEADS 12
#define DHD   64
#define MLPD  3072
#define NPATCH 196
#define ROWS  (BTT*NTOK)    // 7960
#define PROWS (BTT*NPATCH)  // 7840
#define MPAD  8064
#define PPLANE ((size_t)ROWS*DIMD)

// ---------------- scratch (device globals) ----------------
__device__ float  g_x  [ROWS*DIMD];
__device__ float  g_pp [2*ROWS*DIMD];    // split-K partial planes
__device__ __half g_qkvh[MPAD*3*DIMD];
__device__ __half g_ah [MPAD*DIMD];
__device__ __half g_oh [MPAD*DIMD];
__device__ __half g_ffh[MPAD*MLPD];
__device__ __half g_wc  [DIMD*DIMD];
__device__ __half g_wqkv[DEPTH*3*DIMD*DIMD];
__device__ __half g_wo  [DEPTH*DIMD*DIMD];
__device__ __half g_w1  [DEPTH*MLPD*DIMD];
__device__ __half g_w2  [DEPTH*DIMD*MLPD];

// ---------------- helpers ----------------
__device__ __forceinline__ uint32_t smem_u32(const void* p) {
    uint32_t a;
    asm("{ .reg .u64 t; cvta.to.shared.u64 t, %1; cvt.u32.u64 %0, t; }" : "=r"(a) : "l"(p));
    return a;
}
__device__ __forceinline__ float gelu_f(float v) {
    return 0.5f * v * (1.0f + erff(v * 0.70710678118654752f));
}

#define CP16(dst, src)  asm volatile("cp.async.ca.shared.global [%0], [%1], 16;" :: "r"(dst), "l"(src))
#define CP_COMMIT()     asm volatile("cp.async.commit_group;" ::: "memory")
#define CP_WAIT(n)      asm volatile("cp.async.wait_group %0;" :: "n"(n) : "memory")

__device__ __forceinline__ void ldsm4(uint32_t* r, uint32_t a) {
    asm volatile("ldmatrix.sync.aligned.m8n8.x4.shared.b16 {%0,%1,%2,%3}, [%4];"
                 : "=r"(r[0]), "=r"(r[1]), "=r"(r[2]), "=r"(r[3]) : "r"(a));
}
__device__ __forceinline__ void mma16816(float* c, const uint32_t* a, const uint32_t* b) {
    asm volatile("mma.sync.aligned.m16n8k16.row.col.f32.f16.f16.f32 "
                 "{%0,%1,%2,%3}, {%4,%5,%6,%7}, {%8,%9}, {%0,%1,%2,%3};"
                 : "+f"(c[0]), "+f"(c[1]), "+f"(c[2]), "+f"(c[3])
                 : "r"(a[0]), "r"(a[1]), "r"(a[2]), "r"(a[3]), "r"(b[0]), "r"(b[1]));
}

// ---------------- GEMM mainloop: BK=32, 5-stage pipeline, 4 warps 64x64 ----------------
#define ROWB 80
#define TILEB (128*ROWB)              // 10240 B per operand per stage
#define STAGES 5
#define GEMM_SMEM (STAGES*2*TILEB)    // 102400 B -> 2 CTAs/SM

__device__ __forceinline__ void gemm_mainloop(
    float acc[4][8][4], uint32_t sb, int tid, int lane, int wm, int wn,
    const __half* __restrict__ Ag, const __half* __restrict__ Bg,
    int Astride, int Bstride, int T)
{
    #pragma unroll
    for (int i = 0; i < 4; i++)
        #pragma unroll
        for (int j = 0; j < 8; j++)
            #pragma unroll
            for (int q = 0; q < 4; q++) acc[i][j][q] = 0.f;

    auto load_tile = [&](int s, int t) {
        uint32_t abase = sb + s * 2 * TILEB;
        uint32_t bbase = abase + TILEB;
        const __half* Agt = Ag + t * 32;
        const __half* Bgt = Bg + t * 32;
        #pragma unroll
        for (int i = 0; i < 4; i++) {
            int id = tid + i * 128;
            int r = id >> 2, c = id & 3;
            CP16(abase + r * ROWB + c * 16, Agt + (size_t)r * Astride + c * 8);
            CP16(bbase + r * ROWB + c * 16, Bgt + (size_t)r * Bstride + c * 8);
        }
    };

    // preload up to 4 tiles (STAGES-1)
    #pragma unroll
    for (int p = 0; p < STAGES - 1; p++) {
        if (p < T) { load_tile(p, p); CP_COMMIT(); }
    }

    uint32_t a_off = (uint32_t)((wm * 64 + (lane & 15)) * ROWB + (lane >> 4) * 16);
    uint32_t b_off = (uint32_t)((wn * 64 + (lane & 7) + ((lane >> 4) & 1) * 8) * ROWB
                                + ((lane >> 3) & 1) * 16);

    for (int t = 0; t < T; t++) {
        // pending groups: t .. min(t+STAGES-2, T-1). Need group t complete.
        int pending_after = (T - 1) - t;          // groups newer than t still pending
        if (pending_after >= 3)      { CP_WAIT(3); }
        else if (pending_after == 2) { CP_WAIT(2); }
        else if (pending_after == 1) { CP_WAIT(1); }
        else                         { CP_WAIT(0); }
        __syncthreads();
        int buf = t % STAGES;
        if (t + STAGES - 1 < T) { load_tile((t + STAGES - 1) % STAGES, t + STAGES - 1); CP_COMMIT(); }

        uint32_t abase = sb + buf * 2 * TILEB;
        uint32_t bbase = abase + TILEB;
        #pragma unroll
        for (int kk = 0; kk < 2; kk++) {
            uint32_t af[4][4], bf[8][2];
            #pragma unroll
            for (int mi = 0; mi < 4; mi++)
                ldsm4(af[mi], abase + a_off + mi * 16 * ROWB + kk * 32);
            #pragma unroll
            for (int ng = 0; ng < 4; ng++) {
                uint32_t r[4];
                ldsm4(r, bbase + b_off + ng * 16 * ROWB + kk * 32);
                bf[2*ng][0]   = r[0]; bf[2*ng][1]   = r[1];
                bf[2*ng+1][0] = r[2]; bf[2*ng+1][1] = r[3];
            }
            #pragma unroll
            for (int mi = 0; mi < 4; mi++)
                #pragma unroll
                for (int ni = 0; ni < 8; ni++)
                    mma16816(acc[mi][ni], af[mi], bf[ni]);
        }
    }
}

// ---------------- standard epilogue ----------------
// MODE 0: plain fp32; 1: +bias fp32; 3: gelu(+bias)->fp16; 4: plain->fp16
template<int MODE>
__device__ __forceinline__ void epilogue_tile(
    float acc[4][8][4], int bm, int warp_m, int warp_n, int lane,
    const float* __restrict__ bias,
    float* __restrict__ C, __half* __restrict__ Ch, int M, int N)
{
    int lrow = lane >> 2, lcol = (lane & 3) * 2;
    #pragma unroll
    for (int mi = 0; mi < 4; mi++) {
        #pragma unroll
        for (int h = 0; h < 2; h++) {
            int row = bm + warp_m + mi * 16 + lrow + h * 8;
            if (row >= M) continue;
            #pragma unroll
            for (int ni = 0; ni < 8; ni++) {
                int col = warp_n + ni * 8 + lcol;
                float v0 = acc[mi][ni][2*h + 0];
                float v1 = acc[mi][ni][2*h + 1];
                if (MODE == 1 || MODE == 3) { v0 += bias[col]; v1 += bias[col + 1]; }
                if (MODE == 3) {
                    v0 = gelu_f(v0); v1 = gelu_f(v1);
                    *(__half2*)(Ch + (size_t)row * N + col) = __floats2half2_rn(v0, v1);
                } else if (MODE == 4) {
                    *(__half2*)(Ch + (size_t)row * N + col) = __floats2half2_rn(v0, v1);
                } else {
                    *(float2*)(C + (size_t)row * N + col) = make_float2(v0, v1);
                }
            }
        }
    }
}

// ---------------- generic GEMM kernels (2 CTAs/SM) ----------------
template<int MODE>
__global__ __launch_bounds__(128, 2)
void hgemm(const __half* __restrict__ A, const __half* __restrict__ Bw,
           const float* __restrict__ bias,
           float* __restrict__ C, __half* __restrict__ Ch,
           int M, int N, int K)
{
    extern __shared__ char smem[];
    uint32_t sb = smem_u32(smem);
    int tid = threadIdx.x, lane = tid & 31, wid = tid >> 5;
    int wm = wid & 1, wn = wid >> 1;
    int bm = blockIdx.y * 128, bn = blockIdx.x * 128;
    float acc[4][8][4];
    gemm_mainloop(acc, sb, tid, lane, wm, wn,
                  A + (size_t)bm * K, Bw + (size_t)bn * K, K, K, K >> 5);
    epilogue_tile<MODE>(acc, bm, wm * 64, bn + wn * 64, lane, bias, C, Ch, M, N);
}

// split-K: z selects K half + output plane
__global__ __launch_bounds__(128, 2)
void hgemm_sk(const __half* __restrict__ A, const __half* __restrict__ Bw,
              float* __restrict__ C, int M, int N, int Kfull, int Khalf)
{
    extern __shared__ char smem[];
    uint32_t sb = smem_u32(smem);
    int tid = threadIdx.x, lane = tid & 31, wid = tid >> 5;
    int wm = wid & 1, wn = wid >> 1;
    int bm = blockIdx.y * 128, bn = blockIdx.x * 128;
    int z = blockIdx.z;
    float acc[4][8][4];
    gemm_mainloop(acc, sb, tid, lane, wm, wn,
                  A + (size_t)bm * Kfull + z * Khalf,
                  Bw + (size_t)bn * Kfull + z * Khalf,
                  Kfull, Kfull, Khalf >> 5);
    epilogue_tile<0>(acc, bm, wm * 64, bn + wn * 64, lane, nullptr,
                     C + (size_t)z * PPLANE, nullptr, M, N);
}

// patch-embed GEMM with fused assemble
__global__ __launch_bounds__(128, 2)
void hgemm_patch(const __half* __restrict__ A, const __half* __restrict__ Bw,
                 const float* __restrict__ bias, const float* __restrict__ pos,
                 const float* __restrict__ time_emb, float* __restrict__ x)
{
    extern __shared__ char smem[];
    uint32_t sb = smem_u32(smem);
    int tid = threadIdx.x, lane = tid & 31, wid = tid >> 5;
    int wm = wid & 1, wn = wid >> 1;
    int bm = blockIdx.y * 128, bn = blockIdx.x * 128;
    float acc[4][8][4];
    gemm_mainloop(acc, sb, tid, lane, wm, wn,
                  A + (size_t)bm * DIMD, Bw + (size_t)bn * DIMD, DIMD, DIMD, DIMD >> 5);

    int lrow = lane >> 2, lcol = (lane & 3) * 2;
    #pragma unroll
    for (int mi = 0; mi < 4; mi++) {
        #pragma unroll
        for (int h = 0; h < 2; h++) {
            int row = bm + wm * 64 + mi * 16 + lrow + h * 8;
            if (row >= PROWS) continue;
            int bt = row / NPATCH, p = row % NPATCH;
            int tok = p + 1, t = bt % 20;
            float* dst = x + ((size_t)bt * NTOK + tok) * DIMD;
            const float* pr = pos + (size_t)tok * DIMD;
            const float* tr = time_emb + (size_t)t * DIMD;
            #pragma unroll
            for (int ni = 0; ni < 8; ni++) {
                int col = bn + wn * 64 + ni * 8 + lcol;
                float v0 = acc[mi][ni][2*h + 0] + bias[col] + pr[col] + tr[col];
                float v1 = acc[mi][ni][2*h + 1] + bias[col+1] + pr[col+1] + tr[col+1];
                *(float2*)(dst + col) = make_float2(v0, v1);
            }
        }
    }
}

// ---------------- LayerNorm (warp per row) ----------------
__global__ __launch_bounds__(256)
void ln_kernel(const float* __restrict__ x, const float* __restrict__ s,
               const float* __restrict__ b, __half* __restrict__ y, int nrows)
{
    int w = threadIdx.x >> 5, lane = threadIdx.x & 31;
    int row = blockIdx.x * 8 + w;
    if (row >= nrows) return;
    const float4* xr = (const float4*)(x + (size_t)row * DIMD);
    float4 v[6];
    float sum = 0.f;
    #pragma unroll
    for (int j = 0; j < 6; j++) {
        v[j] = xr[j*32 + lane];
        sum += v[j].x + v[j].y + v[j].z + v[j].w;
    }
    #pragma unroll
    for (int off = 16; off; off >>= 1) sum += __shfl_xor_sync(0xffffffffu, sum, off);
    float mean = sum * (1.f/768.f);
    float var = 0.f;
    #pragma unroll
    for (int j = 0; j < 6; j++) {
        v[j].x -= mean; v[j].y -= mean; v[j].z -= mean; v[j].w -= mean;
        var += v[j].x*v[j].x + v[j].y*v[j].y + v[j].z*v[j].z + v[j].w*v[j].w;
    }
    #pragma unroll
    for (int off = 16; off; off >>= 1) var += __shfl_xor_sync(0xffffffffu, var, off);
    float inv = rsqrtf(var * (1.f/768.f) + 1e-5f);
    __half* yr = y + (size_t)row * DIMD;
    #pragma unroll
    for (int j = 0; j < 6; j++) {
        int c = (j*32 + lane) * 4;
        float4 ss = *(const float4*)(s + c);
        float4 bb = *(const float4*)(b + c);
        *(__half2*)(yr + c)     = __floats2half2_rn(v[j].x*inv*ss.x + bb.x, v[j].y*inv*ss.y + bb.y);
        *(__half2*)(yr + c + 2) = __floats2half2_rn(v[j].z*inv*ss.z + bb.z, v[j].w*inv*ss.w + bb.w);
    }
}

// ---------------- fused merge(x += P0+P1+bias) + LayerNorm ----------------
__global__ __launch_bounds__(256)
void ln_merge(float* __restrict__ x, const float* __restrict__ pp,
              const float* __restrict__ gbias, const float* __restrict__ s,
              const float* __restrict__ b, __half* __restrict__ y, int nrows)
{
    int w = threadIdx.x >> 5, lane = threadIdx.x & 31;
    int row = blockIdx.x * 8 + w;
    if (row >= nrows) return;
    float4* xr = (float4*)(x + (size_t)row * DIMD);
    const float4* q0 = (const float4*)(pp + (size_t)row * DIMD);
    const float4* q1 = (const float4*)(pp + PPLANE + (size_t)row * DIMD);
    float4 v[6];
    float sum = 0.f;
    #pragma unroll
    for (int j = 0; j < 6; j++) {
        int c = j*32 + lane;
        float4 a = xr[c], u0 = q0[c], u1 = q1[c];
        float4 gb = *(const float4*)(gbias + c*4);
        v[j].x = a.x + u0.x + u1.x + gb.x;
        v[j].y = a.y + u0.y + u1.y + gb.y;
        v[j].z = a.z + u0.z + u1.z + gb.z;
        v[j].w = a.w + u0.w + u1.w + gb.w;
        xr[c] = v[j];
        sum += v[j].x + v[j].y + v[j].z + v[j].w;
    }
    #pragma unroll
    for (int off = 16; off; off >>= 1) sum += __shfl_xor_sync(0xffffffffu, sum, off);
    float mean = sum * (1.f/768.f);
    float var = 0.f;
    #pragma unroll
    for (int j = 0; j < 6; j++) {
        v[j].x -= mean; v[j].y -= mean; v[j].z -= mean; v[j].w -= mean;
        var += v[j].x*v[j].x + v[j].y*v[j].y + v[j].z*v[j].z + v[j].w*v[j].w;
    }
    #pragma unroll
    for (int off = 16; off; off >>= 1) var += __shfl_xor_sync(0xffffffffu, var, off);
    float inv = rsqrtf(var * (1.f/768.f) + 1e-5f);
    __half* yr = y + (size_t)row * DIMD;
    #pragma unroll
    for (int j = 0; j < 6; j++) {
        int c = (j*32 + lane) * 4;
        float4 ss = *(const float4*)(s + c);
        float4 bb = *(const float4*)(b + c);
        *(__half2*)(yr + c)     = __floats2half2_rn(v[j].x*inv*ss.x + bb.x, v[j].y*inv*ss.y + bb.y);
        *(__half2*)(yr + c + 2) = __floats2half2_rn(v[j].z*inv*ss.z + bb.z, v[j].w*inv*ss.w + bb.w);
    }
}

// ---------------- HMMA attention: one CTA per (seq, head), 4 warps ----------------
#define NT208 208
#define AQP 72
#define AVP 216
#define ATTN_SMEM ((NT208*AQP*2 + 64*AVP) * 2)

__global__ __launch_bounds__(128, 2)
void attn_mma(const __half* __restrict__ qkv, __half* __restrict__ o)
{
    extern __shared__ __half asm_[];
    __half* Qs = asm_;
    __half* Ks = Qs + NT208*AQP;
    __half* Vt = Ks + NT208*AQP;
    uint32_t qb = smem_u32(Qs), kb = smem_u32(Ks), vb = smem_u32(Vt);

    int bt = blockIdx.x / HEADS;
    int hh = blockIdx.x % HEADS;
    const __half* base = qkv + (size_t)bt * NTOK * (3*DIMD) + hh * DHD;
    int tid = threadIdx.x, lane = tid & 31, w = tid >> 5;

    for (int c = tid; c < NT208*8; c += 128) {
        int row = c >> 3, c8 = c & 7;
        uint4 zq = make_uint4(0,0,0,0), zk = zq;
        if (row < NTOK) {
            zq = *(const uint4*)(base + (size_t)row*(3*DIMD) + c8*8);
            zk = *(const uint4*)(base + (size_t)row*(3*DIMD) + DIMD + c8*8);
        }
        *(uint4*)&Qs[row*AQP + c8*8] = zq;
        *(uint4*)&Ks[row*AQP + c8*8] = zk;
    }
    for (int idx = tid; idx < NT208*32; idx += 128) {
        int j = idx >> 5, dp = idx & 31;
        __half2 v = __floats2half2_rn(0.f, 0.f);
        if (j < NTOK) v = *(const __half2*)(base + (size_t)j*(3*DIMD) + 2*DIMD + dp*2);
        Vt[(2*dp)  *AVP + j] = __low2half(v);
        Vt[(2*dp+1)*AVP + j] = __high2half(v);
    }
    __syncthreads();

    uint32_t a_off = (uint32_t)((lane & 15) * 144 + (lane >> 4) * 16);
    uint32_t b_off = (uint32_t)(((lane & 7) + ((lane >> 4) & 1) * 8) * 144 + ((lane >> 3) & 1) * 16);
    uint32_t v_off = (uint32_t)(((lane & 7) + ((lane >> 4) & 1) * 8) * 432 + ((lane >> 3) & 1) * 16);

    int lrow = lane >> 2, lcol = (lane & 3) * 2;

    for (int rt = w; rt < 13; rt += 4) {
        uint32_t qf[4][4];
        #pragma unroll
        for (int kt = 0; kt < 4; kt++)
            ldsm4(qf[kt], qb + (uint32_t)(rt*16*144) + a_off + kt*32);

        float sacc[26][4];
        #pragma unroll
        for (int ni = 0; ni < 26; ni++)
            #pragma unroll
            for (int q = 0; q < 4; q++) sacc[ni][q] = 0.f;
        #pragma unroll
        for (int kt = 0; kt < 4; kt++) {
            #pragma unroll
            for (int ng = 0; ng < 13; ng++) {
                uint32_t r[4], bf0[2], bf1[2];
                ldsm4(r, kb + (uint32_t)(ng*16*144) + b_off + kt*32);
                bf0[0] = r[0]; bf0[1] = r[1];
                bf1[0] = r[2]; bf1[1] = r[3];
                mma16816(sacc[2*ng],   qf[kt], bf0);
                mma16816(sacc[2*ng+1], qf[kt], bf1);
            }
        }
        #pragma unroll
        for (int ni = 0; ni < 26; ni++) {
            int gc = ni*8 + lcol;
            #pragma unroll
            for (int q = 0; q < 4; q++) {
                int col = gc + (q & 1);
                sacc[ni][q] = (col < NTOK) ? sacc[ni][q] * 0.125f : -1e30f;
            }
        }
        float mxA = -1e30f, mxB = -1e30f;
        #pragma unroll
        for (int ni = 0; ni < 26; ni++) {
            mxA = fmaxf(mxA, fmaxf(sacc[ni][0], sacc[ni][1]));
            mxB = fmaxf(mxB, fmaxf(sacc[ni][2], sacc[ni][3]));
        }
        mxA = fmaxf(mxA, __shfl_xor_sync(0xffffffffu, mxA, 1));
        mxA = fmaxf(mxA, __shfl_xor_sync(0xffffffffu, mxA, 2));
        mxB = fmaxf(mxB, __shfl_xor_sync(0xffffffffu, mxB, 1));
        mxB = fmaxf(mxB, __shfl_xor_sync(0xffffffffu, mxB, 2));
        float sA = 0.f, sB = 0.f;
        #pragma unroll
        for (int ni = 0; ni < 26; ni++) {
            sacc[ni][0] = __expf(sacc[ni][0] - mxA);
            sacc[ni][1] = __expf(sacc[ni][1] - mxA);
            sacc[ni][2] = __expf(sacc[ni][2] - mxB);
            sacc[ni][3] = __expf(sacc[ni][3] - mxB);
            sA += sacc[ni][0] + sacc[ni][1];
            sB += sacc[ni][2] + sacc[ni][3];
        }
        sA += __shfl_xor_sync(0xffffffffu, sA, 1);
        sA += __shfl_xor_sync(0xffffffffu, sA, 2);
        sB += __shfl_xor_sync(0xffffffffu, sB, 1);
        sB += __shfl_xor_sync(0xffffffffu, sB, 2);
        float rA = 1.f / sA, rB = 1.f / sB;

        uint32_t pf[13][4];
        #pragma unroll
        for (int kt = 0; kt < 13; kt++) {
            __half2 h;
            h = __floats2half2_rn(sacc[2*kt][0],   sacc[2*kt][1]);   pf[kt][0] = *(uint32_t*)&h;
            h = __floats2half2_rn(sacc[2*kt][2],   sacc[2*kt][3]);   pf[kt][1] = *(uint32_t*)&h;
            h = __floats2half2_rn(sacc[2*kt+1][0], sacc[2*kt+1][1]); pf[kt][2] = *(uint32_t*)&h;
            h = __floats2half2_rn(sacc[2*kt+1][2], sacc[2*kt+1][3]); pf[kt][3] = *(uint32_t*)&h;
        }

        float oacc[8][4];
        #pragma unroll
        for (int ni = 0; ni < 8; ni++)
            #pragma unroll
            for (int q = 0; q < 4; q++) oacc[ni][q] = 0.f;
        #pragma unroll
        for (int kt = 0; kt < 13; kt++) {
            #pragma unroll
            for (int ng = 0; ng < 4; ng++) {
                uint32_t r[4], bf0[2], bf1[2];
                ldsm4(r, vb + (uint32_t)(ng*16*432) + v_off + kt*32);
                bf0[0] = r[0]; bf0[1] = r[1];
                bf1[0] = r[2]; bf1[1] = r[3];
                mma16816(oacc[2*ng],   pf[kt], bf0);
                mma16816(oacc[2*ng+1], pf[kt], bf1);
            }
        }
        int row0 = rt*16 + lrow, row1 = row0 + 8;
        __half* ob = o + ((size_t)bt*NTOK)*DIMD + hh*DHD;
        #pragma unroll
        for (int ni = 0; ni < 8; ni++) {
            int gc = ni*8 + lcol;
            if (row0 < NTOK) {
                *(__half2*)(ob + (size_t)row0*DIMD + gc) =
                    __floats2half2_rn(oacc[ni][0]*rA, oacc[ni][1]*rA);
            }
            if (row1 < NTOK) {
                *(__half2*)(ob + (size_t)row1*DIMD + gc) =
                    __floats2half2_rn(oacc[ni][2]*rB, oacc[ni][3]*rB);
            }
        }
    }
}

// ---------------- fused weight prep ----------------
#define PREP_BLOCKS 83520
__global__ void prep_weights(const float* __restrict__ conv_w, const float* __restrict__ qkv_w,
                             const float* __restrict__ out_w, const float* __restrict__ ff_w1,
                             const float* __restrict__ ff_w2,
                             __half* __restrict__ wc, __half* __restrict__ wqkv,
                             __half* __restrict__ wo, __half* __restrict__ w1,
                             __half* __restrict__ w2)
{
    __shared__ float tbuf[32][33];
    int b = blockIdx.x;
    int tx = threadIdx.x, ty = threadIdx.y;
    if (b < 576) {
        int r0 = (b/24)*32, c0 = (b%24)*32;
        for (int i = ty; i < 32; i += 8) {
            int idx = (r0+i)*768 + c0 + tx;
            wc[idx] = __float2half(conv_w[idx]);
        }
        return;
    }
    const float* src; __half* dst; int K, N, tl;
    if (b < 21312)      { int t = b-576;   int L=1728; int layer=t/L; tl=t%L; K=768;  N=2304; src=qkv_w+(size_t)layer*K*N; dst=wqkv+(size_t)layer*K*N; }
    else if (b < 28224) { int t = b-21312; int L=576;  int layer=t/L; tl=t%L; K=768;  N=768;  src=out_w+(size_t)layer*K*N; dst=wo  +(size_t)layer*K*N; }
    else if (b < 55872) { int t = b-28224; int L=2304; int layer=t/L; tl=t%L; K=768;  N=3072; src=ff_w1+(size_t)layer*K*N; dst=w1  +(size_t)layer*K*N; }
    else                { int t = b-55872; int L=2304; int layer=t/L; tl=t%L; K=3072; N=768;  src=ff_w2+(size_t)layer*K*N; dst=w2  +(size_t)layer*K*N; }
    int ntn = N / 32;
    int k0 = (tl / ntn) * 32, n0 = (tl % ntn) * 32;
    for (int i = ty; i < 32; i += 8)
        tbuf[i][tx] = src[(size_t)(k0+i)*N + n0 + tx];
    __syncthreads();
    for (int i = ty; i < 32; i += 8)
        dst[(size_t)(n0+i)*K + k0 + tx] = __float2half(tbuf[tx][i]);
}

// ---------------- small kernels ----------------
__global__ void im2col_kernel(const float* __restrict__ img, __half* __restrict__ pv)
{
    int idx = blockIdx.x*256 + threadIdx.x;
    if (idx >= PROWS*DIMD) return;
    int k   = idx % DIMD;
    int row = idx / DIMD;
    int bt = row / NPATCH, p = row % NPATCH;
    int c = k >> 8, rem = k & 255, ii = rem >> 4, jj = rem & 15;
    int ph = p / 14, pw = p % 14;
    pv[idx] = __float2half(img[(((size_t)bt*3 + c)*224 + ph*16 + ii)*224 + pw*16 + jj]);
}

__global__ void clsface_kernel(const float* __restrict__ face, const float* __restrict__ pos,
                               const float* __restrict__ time_emb, const float* __restrict__ cls,
                               float* __restrict__ x)
{
    int idx = blockIdx.x*256 + threadIdx.x;
    if (idx >= BTT*3*DIMD) return;
    int n   = idx % DIMD;
    int rem = idx / DIMD;
    int which = rem % 3;
    int bt  = rem / 3;
    int t   = bt % 20;
    float v; int tok;
    if (which == 0)      { tok = 0;   v = cls[n] + pos[n]; }
    else if (which == 1) { tok = 197; v = face[((size_t)bt*2 + 0)*DIMD + n]; }
    else                 { tok = 198; v = face[((size_t)bt*2 + 1)*DIMD + n]; }
    x[((size_t)bt*NTOK + tok)*DIMD + n] = v + time_emb[t*DIMD + n];
}

// ---------------- output extraction with final FF2 merge ----------------
#define OUT_TOT (3*BTT*DIMD + BTT*NPATCH*DIMD)
__global__ void extract_merge(const float* __restrict__ x, const float* __restrict__ pp,
                              const float* __restrict__ gbias, float* __restrict__ out)
{
    int idx = blockIdx.x*256 + threadIdx.x;
    const int P = BTT*DIMD;
    if (idx >= OUT_TOT) return;
    int bt, tok, n;
    if (idx < 3*P) {
        int part = idx / P;
        int r = idx % P;
        bt = r / DIMD; n = r % DIMD;
        tok = (part == 0) ? 0 : (part == 1 ? 197 : 198);
    } else {
        int r = idx - 3*P;
        n  = r % DIMD;
        tok = 1 + (r / DIMD) % NPATCH;
        bt = r / (DIMD*NPATCH);
    }
    size_t off = ((size_t)bt*NTOK + tok)*DIMD + n;
    out[idx] = x[off] + pp[off] + pp[PPLANE + off] + gbias[n];
}

// ---------------- host ----------------
static void launch_hgemm(int mode, const __half* A, const __half* B, const float* bias,
                         float* C, __half* Ch, int M, int N, int K)
{
    dim3 grid(N/128, (M + 127)/128);
    switch (mode) {
        case 3: hgemm<3><<<grid, 128, GEMM_SMEM>>>(A, B, bias, C, Ch, M, N, K); break;
        case 4: hgemm<4><<<grid, 128, GEMM_SMEM>>>(A, B, bias, C, Ch, M, N, K); break;
    }
}

extern "C" void kernel_launch(void* const* d_in, const int* in_sizes, int n_in,
                              void* d_out, int out_size)
{
    (void)in_sizes; (void)n_in; (void)out_size;
    const float* img      = (const float*)d_in[0];
    const float* face     = (const float*)d_in[1];
    const float* conv_w   = (const float*)d_in[2];
    const float* conv_b   = (const float*)d_in[3];
    const float* pos_emb  = (const float*)d_in[4];
    const float* time_emb = (const float*)d_in[5];
    const float* cls_tok  = (const float*)d_in[6];
    const float* ln1_s    = (const float*)d_in[7];
    const float* ln1_b    = (const float*)d_in[8];
    const float* qkv_w    = (const float*)d_in[9];
    const float* out_w    = (const float*)d_in[10];
    const float* out_b    = (const float*)d_in[11];
    const float* ln2_s    = (const float*)d_in[12];
    const float* ln2_b    = (const float*)d_in[13];
    const float* ff_w1    = (const float*)d_in[14];
    const float* ff_b1    = (const float*)d_in[15];
    const float* ff_w2    = (const float*)d_in[16];
    const float* ff_b2    = (const float*)d_in[17];
    float* out = (float*)d_out;

    float *gx, *gpp;
    __half *gqkvh, *gah, *goh, *gffh, *gwc, *gwqkv, *gwo, *gw1, *gw2;
    cudaGetSymbolAddress((void**)&gx,    g_x);
    cudaGetSymbolAddress((void**)&gpp,   g_pp);
    cudaGetSymbolAddress((void**)&gqkvh, g_qkvh);
    cudaGetSymbolAddress((void**)&gah,   g_ah);
    cudaGetSymbolAddress((void**)&goh,   g_oh);
    cudaGetSymbolAddress((void**)&gffh,  g_ffh);
    cudaGetSymbolAddress((void**)&gwc,   g_wc);
    cudaGetSymbolAddress((void**)&gwqkv, g_wqkv);
    cudaGetSymbolAddress((void**)&gwo,   g_wo);
    cudaGetSymbolAddress((void**)&gw1,   g_w1);
    cudaGetSymbolAddress((void**)&gw2,   g_w2);

    cudaFuncSetAttribute(attn_mma, cudaFuncAttributeMaxDynamicSharedMemorySize, ATTN_SMEM);
    cudaFuncSetAttribute(hgemm<3>, cudaFuncAttributeMaxDynamicSharedMemorySize, GEMM_SMEM);
    cudaFuncSetAttribute(hgemm<4>, cudaFuncAttributeMaxDynamicSharedMemorySize, GEMM_SMEM);
    cudaFuncSetAttribute(hgemm_sk, cudaFuncAttributeMaxDynamicSharedMemorySize, GEMM_SMEM);
    cudaFuncSetAttribute(hgemm_patch, cudaFuncAttributeMaxDynamicSharedMemorySize, GEMM_SMEM);

    prep_weights<<<PREP_BLOCKS, dim3(32,8)>>>(conv_w, qkv_w, out_w, ff_w1, ff_w2,
                                              gwc, gwqkv, gwo, gw1, gw2);
    im2col_kernel<<<(PROWS*DIMD + 255)/256, 256>>>(img, gah);
    clsface_kernel<<<(BTT*3*DIMD + 255)/256, 256>>>(face, pos_emb, time_emb, cls_tok, gx);
    // #4: patch GEMM (ncu capture slot)
    hgemm_patch<<<dim3(DIMD/128, (PROWS+127)/128), 128, GEMM_SMEM>>>(
        gah, gwc, conv_b, pos_emb, time_emb, gx);

    const int LNB = (ROWS + 7)/8;
    for (int l = 0; l < DEPTH; l++) {
        if (l == 0)
            ln_kernel<<<LNB, 256>>>(gx, ln1_s, ln1_b, gah, ROWS);
        else
            ln_merge<<<LNB, 256>>>(gx, gpp, ff_b2 + (l-1)*DIMD,
                                   ln1_s + l*DIMD, ln1_b + l*DIMD, gah, ROWS);
        launch_hgemm(4, gah, gwqkv + (size_t)l*3*DIMD*DIMD, nullptr,
                     nullptr, gqkvh, ROWS, 3*DIMD, DIMD);
        attn_mma<<<BTT*HEADS, 128, ATTN_SMEM>>>(gqkvh, goh);
        hgemm_sk<<<dim3(DIMD/128, (ROWS+127)/128, 2), 128, GEMM_SMEM>>>(
            goh, gwo + (size_t)l*DIMD*DIMD, gpp, ROWS, DIMD, DIMD, DIMD/2);
        ln_merge<<<LNB, 256>>>(gx, gpp, out_b + l*DIMD,
                               ln2_s + l*DIMD, ln2_b + l*DIMD, gah, ROWS);
        launch_hgemm(3, gah, gw1 + (size_t)l*MLPD*DIMD, ff_b1 + l*MLPD,
                     nullptr, gffh, ROWS, MLPD, DIMD);
        hgemm_sk<<<dim3(DIMD/128, (ROWS+127)/128, 2), 128, GEMM_SMEM>>>(
            gffh, gw2 + (size_t)l*DIMD*MLPD, gpp, ROWS, DIMD, MLPD, MLPD/2);
    }

    extract_merge<<<(OUT_TOT + 255)/256, 256>>>(gx, gpp, ff_b2 + 11*DIMD, out);
}

// round 15
// speedup vs baseline: 1.2604x; 1.2604x over previous
#include <cuda_runtime.h>
#include <cuda_fp16.h>
#include <math.h>
#include <stdint.h>

// ---------------- problem constants ----------------
#define BTT   40
#define NTOK  199
#define DIMD  768
#define DEPTH 12
#define HEADS 12
#define DHD   64
#define MLPD  3072
#define NPATCH 196
#define ROWS  (BTT*NTOK)    // 7960
#define PROWS (BTT*NPATCH)  // 7840
#define MPAD  8064
#define PPLANE ((size_t)ROWS*DIMD)

// ---------------- scratch (device globals) ----------------
__device__ float  g_x  [ROWS*DIMD];
__device__ float  g_pp [2*ROWS*DIMD];    // split-K partial planes
__device__ __half g_qkvh[MPAD*3*DIMD];
__device__ __half g_ah [MPAD*DIMD];
__device__ __half g_oh [MPAD*DIMD];
__device__ __half g_ffh[MPAD*MLPD];
__device__ __half g_wc  [DIMD*DIMD];
__device__ __half g_wqkv[DEPTH*3*DIMD*DIMD];
__device__ __half g_wo  [DEPTH*DIMD*DIMD];
__device__ __half g_w1  [DEPTH*MLPD*DIMD];
__device__ __half g_w2  [DEPTH*DIMD*MLPD];

// ---------------- helpers ----------------
__device__ __forceinline__ uint32_t smem_u32(const void* p) {
    uint32_t a;
    asm("{ .reg .u64 t; cvta.to.shared.u64 t, %1; cvt.u32.u64 %0, t; }" : "=r"(a) : "l"(p));
    return a;
}
__device__ __forceinline__ float gelu_f(float v) {
    return 0.5f * v * (1.0f + erff(v * 0.70710678118654752f));
}

#define CP16(dst, src)  asm volatile("cp.async.ca.shared.global [%0], [%1], 16;" :: "r"(dst), "l"(src))
#define CP_COMMIT()     asm volatile("cp.async.commit_group;" ::: "memory")
#define CP_WAIT(n)      asm volatile("cp.async.wait_group %0;" :: "n"(n) : "memory")

__device__ __forceinline__ void ldsm4(uint32_t* r, uint32_t a) {
    asm volatile("ldmatrix.sync.aligned.m8n8.x4.shared.b16 {%0,%1,%2,%3}, [%4];"
                 : "=r"(r[0]), "=r"(r[1]), "=r"(r[2]), "=r"(r[3]) : "r"(a));
}
__device__ __forceinline__ void mma16816(float* c, const uint32_t* a, const uint32_t* b) {
    asm volatile("mma.sync.aligned.m16n8k16.row.col.f32.f16.f16.f32 "
                 "{%0,%1,%2,%3}, {%4,%5,%6,%7}, {%8,%9}, {%0,%1,%2,%3};"
                 : "+f"(c[0]), "+f"(c[1]), "+f"(c[2]), "+f"(c[3])
                 : "r"(a[0]), "r"(a[1]), "r"(a[2]), "r"(a[3]), "r"(b[0]), "r"(b[1]));
}

// ---------------- GEMM mainloop (R10 config: BK=32, 3-stage, 4 warps 64x64) ----------------
#define ROWB 80
#define TILEB (128*ROWB)
#define GEMM_SMEM (3*2*TILEB)

__device__ __forceinline__ void gemm_mainloop(
    float acc[4][8][4], uint32_t sb, int tid, int lane, int wm, int wn,
    const __half* __restrict__ Ag, const __half* __restrict__ Bg,
    int Astride, int Bstride, int T)
{
    #pragma unroll
    for (int i = 0; i < 4; i++)
        #pragma unroll
        for (int j = 0; j < 8; j++)
            #pragma unroll
            for (int q = 0; q < 4; q++) acc[i][j][q] = 0.f;

    auto load_tile = [&](int s, int t) {
        uint32_t abase = sb + s * 2 * TILEB;
        uint32_t bbase = abase + TILEB;
        const __half* Agt = Ag + t * 32;
        const __half* Bgt = Bg + t * 32;
        #pragma unroll
        for (int i = 0; i < 4; i++) {
            int id = tid + i * 128;
            int r = id >> 2, c = id & 3;
            CP16(abase + r * ROWB + c * 16, Agt + (size_t)r * Astride + c * 8);
            CP16(bbase + r * ROWB + c * 16, Bgt + (size_t)r * Bstride + c * 8);
        }
    };

    load_tile(0, 0); CP_COMMIT();
    if (T > 1) { load_tile(1, 1); CP_COMMIT(); }

    uint32_t a_off = (uint32_t)((wm * 64 + (lane & 15)) * ROWB + (lane >> 4) * 16);
    uint32_t b_off = (uint32_t)((wn * 64 + (lane & 7) + ((lane >> 4) & 1) * 8) * ROWB
                                + ((lane >> 3) & 1) * 16);

    for (int t = 0; t < T; t++) {
        if (t == T - 1) { CP_WAIT(0); } else { CP_WAIT(1); }
        __syncthreads();
        int buf = t % 3;
        if (t + 2 < T) { load_tile((t + 2) % 3, t + 2); CP_COMMIT(); }

        uint32_t abase = sb + buf * 2 * TILEB;
        uint32_t bbase = abase + TILEB;
        #pragma unroll
        for (int kk = 0; kk < 2; kk++) {
            uint32_t af[4][4], bf[8][2];
            #pragma unroll
            for (int mi = 0; mi < 4; mi++)
                ldsm4(af[mi], abase + a_off + mi * 16 * ROWB + kk * 32);
            #pragma unroll
            for (int ng = 0; ng < 4; ng++) {
                uint32_t r[4];
                ldsm4(r, bbase + b_off + ng * 16 * ROWB + kk * 32);
                bf[2*ng][0]   = r[0]; bf[2*ng][1]   = r[1];
                bf[2*ng+1][0] = r[2]; bf[2*ng+1][1] = r[3];
            }
            #pragma unroll
            for (int mi = 0; mi < 4; mi++)
                #pragma unroll
                for (int ni = 0; ni < 8; ni++)
                    mma16816(acc[mi][ni], af[mi], bf[ni]);
        }
    }
}

// ---------------- standard epilogue ----------------
// MODE 0: plain fp32; 1: +bias fp32; 3: gelu(+bias)->fp16; 4: plain->fp16
template<int MODE>
__device__ __forceinline__ void epilogue_tile(
    float acc[4][8][4], int bm, int warp_m, int warp_n, int lane,
    const float* __restrict__ bias,
    float* __restrict__ C, __half* __restrict__ Ch, int M, int N)
{
    int lrow = lane >> 2, lcol = (lane & 3) * 2;
    #pragma unroll
    for (int mi = 0; mi < 4; mi++) {
        #pragma unroll
        for (int h = 0; h < 2; h++) {
            int row = bm + warp_m + mi * 16 + lrow + h * 8;
            if (row >= M) continue;
            #pragma unroll
            for (int ni = 0; ni < 8; ni++) {
                int col = warp_n + ni * 8 + lcol;
                float v0 = acc[mi][ni][2*h + 0];
                float v1 = acc[mi][ni][2*h + 1];
                if (MODE == 1 || MODE == 3) { v0 += bias[col]; v1 += bias[col + 1]; }
                if (MODE == 3) {
                    v0 = gelu_f(v0); v1 = gelu_f(v1);
                    *(__half2*)(Ch + (size_t)row * N + col) = __floats2half2_rn(v0, v1);
                } else if (MODE == 4) {
                    *(__half2*)(Ch + (size_t)row * N + col) = __floats2half2_rn(v0, v1);
                } else {
                    *(float2*)(C + (size_t)row * N + col) = make_float2(v0, v1);
                }
            }
        }
    }
}

// ---------------- generic GEMM kernels (2 CTAs/SM) ----------------
template<int MODE>
__global__ __launch_bounds__(128, 2)
void hgemm(const __half* __restrict__ A, const __half* __restrict__ Bw,
           const float* __restrict__ bias,
           float* __restrict__ C, __half* __restrict__ Ch,
           int M, int N, int K)
{
    extern __shared__ char smem[];
    uint32_t sb = smem_u32(smem);
    int tid = threadIdx.x, lane = tid & 31, wid = tid >> 5;
    int wm = wid & 1, wn = wid >> 1;
    int bm = blockIdx.y * 128, bn = blockIdx.x * 128;
    float acc[4][8][4];
    gemm_mainloop(acc, sb, tid, lane, wm, wn,
                  A + (size_t)bm * K, Bw + (size_t)bn * K, K, K, K >> 5);
    epilogue_tile<MODE>(acc, bm, wm * 64, bn + wn * 64, lane, bias, C, Ch, M, N);
}

// split-K: z selects K half + output plane
__global__ __launch_bounds__(128, 2)
void hgemm_sk(const __half* __restrict__ A, const __half* __restrict__ Bw,
              float* __restrict__ C, int M, int N, int Kfull, int Khalf)
{
    extern __shared__ char smem[];
    uint32_t sb = smem_u32(smem);
    int tid = threadIdx.x, lane = tid & 31, wid = tid >> 5;
    int wm = wid & 1, wn = wid >> 1;
    int bm = blockIdx.y * 128, bn = blockIdx.x * 128;
    int z = blockIdx.z;
    float acc[4][8][4];
    gemm_mainloop(acc, sb, tid, lane, wm, wn,
                  A + (size_t)bm * Kfull + z * Khalf,
                  Bw + (size_t)bn * Kfull + z * Khalf,
                  Kfull, Kfull, Khalf >> 5);
    epilogue_tile<0>(acc, bm, wm * 64, bn + wn * 64, lane, nullptr,
                     C + (size_t)z * PPLANE, nullptr, M, N);
}

// patch-embed GEMM with fused assemble
__global__ __launch_bounds__(128, 2)
void hgemm_patch(const __half* __restrict__ A, const __half* __restrict__ Bw,
                 const float* __restrict__ bias, const float* __restrict__ pos,
                 const float* __restrict__ time_emb, float* __restrict__ x)
{
    extern __shared__ char smem[];
    uint32_t sb = smem_u32(smem);
    int tid = threadIdx.x, lane = tid & 31, wid = tid >> 5;
    int wm = wid & 1, wn = wid >> 1;
    int bm = blockIdx.y * 128, bn = blockIdx.x * 128;
    float acc[4][8][4];
    gemm_mainloop(acc, sb, tid, lane, wm, wn,
                  A + (size_t)bm * DIMD, Bw + (size_t)bn * DIMD, DIMD, DIMD, DIMD >> 5);

    int lrow = lane >> 2, lcol = (lane & 3) * 2;
    #pragma unroll
    for (int mi = 0; mi < 4; mi++) {
        #pragma unroll
        for (int h = 0; h < 2; h++) {
            int row = bm + wm * 64 + mi * 16 + lrow + h * 8;
            if (row >= PROWS) continue;
            int bt = row / NPATCH, p = row % NPATCH;
            int tok = p + 1, t = bt % 20;
            float* dst = x + ((size_t)bt * NTOK + tok) * DIMD;
            const float* pr = pos + (size_t)tok * DIMD;
            const float* tr = time_emb + (size_t)t * DIMD;
            #pragma unroll
            for (int ni = 0; ni < 8; ni++) {
                int col = bn + wn * 64 + ni * 8 + lcol;
                float v0 = acc[mi][ni][2*h + 0] + bias[col] + pr[col] + tr[col];
                float v1 = acc[mi][ni][2*h + 1] + bias[col+1] + pr[col+1] + tr[col+1];
                *(float2*)(dst + col) = make_float2(v0, v1);
            }
        }
    }
}

// ---------------- LayerNorm (warp per row) ----------------
__global__ __launch_bounds__(256)
void ln_kernel(const float* __restrict__ x, const float* __restrict__ s,
               const float* __restrict__ b, __half* __restrict__ y, int nrows)
{
    int w = threadIdx.x >> 5, lane = threadIdx.x & 31;
    int row = blockIdx.x * 8 + w;
    if (row >= nrows) return;
    const float4* xr = (const float4*)(x + (size_t)row * DIMD);
    float4 v[6];
    float sum = 0.f;
    #pragma unroll
    for (int j = 0; j < 6; j++) {
        v[j] = xr[j*32 + lane];
        sum += v[j].x + v[j].y + v[j].z + v[j].w;
    }
    #pragma unroll
    for (int off = 16; off; off >>= 1) sum += __shfl_xor_sync(0xffffffffu, sum, off);
    float mean = sum * (1.f/768.f);
    float var = 0.f;
    #pragma unroll
    for (int j = 0; j < 6; j++) {
        v[j].x -= mean; v[j].y -= mean; v[j].z -= mean; v[j].w -= mean;
        var += v[j].x*v[j].x + v[j].y*v[j].y + v[j].z*v[j].z + v[j].w*v[j].w;
    }
    #pragma unroll
    for (int off = 16; off; off >>= 1) var += __shfl_xor_sync(0xffffffffu, var, off);
    float inv = rsqrtf(var * (1.f/768.f) + 1e-5f);
    __half* yr = y + (size_t)row * DIMD;
    #pragma unroll
    for (int j = 0; j < 6; j++) {
        int c = (j*32 + lane) * 4;
        float4 ss = *(const float4*)(s + c);
        float4 bb = *(const float4*)(b + c);
        *(__half2*)(yr + c)     = __floats2half2_rn(v[j].x*inv*ss.x + bb.x, v[j].y*inv*ss.y + bb.y);
        *(__half2*)(yr + c + 2) = __floats2half2_rn(v[j].z*inv*ss.z + bb.z, v[j].w*inv*ss.w + bb.w);
    }
}

// ---------------- fused merge(x += P0+P1+bias) + LayerNorm ----------------
__global__ __launch_bounds__(256)
void ln_merge(float* __restrict__ x, const float* __restrict__ pp,
              const float* __restrict__ gbias, const float* __restrict__ s,
              const float* __restrict__ b, __half* __restrict__ y, int nrows)
{
    int w = threadIdx.x >> 5, lane = threadIdx.x & 31;
    int row = blockIdx.x * 8 + w;
    if (row >= nrows) return;
    float4* xr = (float4*)(x + (size_t)row * DIMD);
    const float4* q0 = (const float4*)(pp + (size_t)row * DIMD);
    const float4* q1 = (const float4*)(pp + PPLANE + (size_t)row * DIMD);
    float4 v[6];
    float sum = 0.f;
    #pragma unroll
    for (int j = 0; j < 6; j++) {
        int c = j*32 + lane;
        float4 a = xr[c], u0 = q0[c], u1 = q1[c];
        float4 gb = *(const float4*)(gbias + c*4);
        v[j].x = a.x + u0.x + u1.x + gb.x;
        v[j].y = a.y + u0.y + u1.y + gb.y;
        v[j].z = a.z + u0.z + u1.z + gb.z;
        v[j].w = a.w + u0.w + u1.w + gb.w;
        xr[c] = v[j];
        sum += v[j].x + v[j].y + v[j].z + v[j].w;
    }
    #pragma unroll
    for (int off = 16; off; off >>= 1) sum += __shfl_xor_sync(0xffffffffu, sum, off);
    float mean = sum * (1.f/768.f);
    float var = 0.f;
    #pragma unroll
    for (int j = 0; j < 6; j++) {
        v[j].x -= mean; v[j].y -= mean; v[j].z -= mean; v[j].w -= mean;
        var += v[j].x*v[j].x + v[j].y*v[j].y + v[j].z*v[j].z + v[j].w*v[j].w;
    }
    #pragma unroll
    for (int off = 16; off; off >>= 1) var += __shfl_xor_sync(0xffffffffu, var, off);
    float inv = rsqrtf(var * (1.f/768.f) + 1e-5f);
    __half* yr = y + (size_t)row * DIMD;
    #pragma unroll
    for (int j = 0; j < 6; j++) {
        int c = (j*32 + lane) * 4;
        float4 ss = *(const float4*)(s + c);
        float4 bb = *(const float4*)(b + c);
        *(__half2*)(yr + c)     = __floats2half2_rn(v[j].x*inv*ss.x + bb.x, v[j].y*inv*ss.y + bb.y);
        *(__half2*)(yr + c + 2) = __floats2half2_rn(v[j].z*inv*ss.z + bb.z, v[j].w*inv*ss.w + bb.w);
    }
}

// ---------------- HMMA attention: one CTA per (seq, head), 4 warps ----------------
#define NT208 208
#define AQP 72
#define AVP 216
#define ATTN_SMEM ((NT208*AQP*2 + 64*AVP) * 2)

__global__ __launch_bounds__(128, 2)
void attn_mma(const __half* __restrict__ qkv, __half* __restrict__ o)
{
    extern __shared__ __half asm_[];
    __half* Qs = asm_;
    __half* Ks = Qs + NT208*AQP;
    __half* Vt = Ks + NT208*AQP;
    uint32_t qb = smem_u32(Qs), kb = smem_u32(Ks), vb = smem_u32(Vt);

    int bt = blockIdx.x / HEADS;
    int hh = blockIdx.x % HEADS;
    const __half* base = qkv + (size_t)bt * NTOK * (3*DIMD) + hh * DHD;
    int tid = threadIdx.x, lane = tid & 31, w = tid >> 5;

    for (int c = tid; c < NT208*8; c += 128) {
        int row = c >> 3, c8 = c & 7;
        uint4 zq = make_uint4(0,0,0,0), zk = zq;
        if (row < NTOK) {
            zq = *(const uint4*)(base + (size_t)row*(3*DIMD) + c8*8);
            zk = *(const uint4*)(base + (size_t)row*(3*DIMD) + DIMD + c8*8);
        }
        *(uint4*)&Qs[row*AQP + c8*8] = zq;
        *(uint4*)&Ks[row*AQP + c8*8] = zk;
    }
    for (int idx = tid; idx < NT208*32; idx += 128) {
        int j = idx >> 5, dp = idx & 31;
        __half2 v = __floats2half2_rn(0.f, 0.f);
        if (j < NTOK) v = *(const __half2*)(base + (size_t)j*(3*DIMD) + 2*DIMD + dp*2);
        Vt[(2*dp)  *AVP + j] = __low2half(v);
        Vt[(2*dp+1)*AVP + j] = __high2half(v);
    }
    __syncthreads();

    uint32_t a_off = (uint32_t)((lane & 15) * 144 + (lane >> 4) * 16);
    uint32_t b_off = (uint32_t)(((lane & 7) + ((lane >> 4) & 1) * 8) * 144 + ((lane >> 3) & 1) * 16);
    uint32_t v_off = (uint32_t)(((lane & 7) + ((lane >> 4) & 1) * 8) * 432 + ((lane >> 3) & 1) * 16);

    int lrow = lane >> 2, lcol = (lane & 3) * 2;

    for (int rt = w; rt < 13; rt += 4) {
        uint32_t qf[4][4];
        #pragma unroll
        for (int kt = 0; kt < 4; kt++)
            ldsm4(qf[kt], qb + (uint32_t)(rt*16*144) + a_off + kt*32);

        float sacc[26][4];
        #pragma unroll
        for (int ni = 0; ni < 26; ni++)
            #pragma unroll
            for (int q = 0; q < 4; q++) sacc[ni][q] = 0.f;
        #pragma unroll
        for (int kt = 0; kt < 4; kt++) {
            #pragma unroll
            for (int ng = 0; ng < 13; ng++) {
                uint32_t r[4], bf0[2], bf1[2];
                ldsm4(r, kb + (uint32_t)(ng*16*144) + b_off + kt*32);
                bf0[0] = r[0]; bf0[1] = r[1];
                bf1[0] = r[2]; bf1[1] = r[3];
                mma16816(sacc[2*ng],   qf[kt], bf0);
                mma16816(sacc[2*ng+1], qf[kt], bf1);
            }
        }
        #pragma unroll
        for (int ni = 0; ni < 26; ni++) {
            int gc = ni*8 + lcol;
            #pragma unroll
            for (int q = 0; q < 4; q++) {
                int col = gc + (q & 1);
                sacc[ni][q] = (col < NTOK) ? sacc[ni][q] * 0.125f : -1e30f;
            }
        }
        float mxA = -1e30f, mxB = -1e30f;
        #pragma unroll
        for (int ni = 0; ni < 26; ni++) {
            mxA = fmaxf(mxA, fmaxf(sacc[ni][0], sacc[ni][1]));
            mxB = fmaxf(mxB, fmaxf(sacc[ni][2], sacc[ni][3]));
        }
        mxA = fmaxf(mxA, __shfl_xor_sync(0xffffffffu, mxA, 1));
        mxA = fmaxf(mxA, __shfl_xor_sync(0xffffffffu, mxA, 2));
        mxB = fmaxf(mxB, __shfl_xor_sync(0xffffffffu, mxB, 1));
        mxB = fmaxf(mxB, __shfl_xor_sync(0xffffffffu, mxB, 2));
        float sA = 0.f, sB = 0.f;
        #pragma unroll
        for (int ni = 0; ni < 26; ni++) {
            sacc[ni][0] = __expf(sacc[ni][0] - mxA);
            sacc[ni][1] = __expf(sacc[ni][1] - mxA);
            sacc[ni][2] = __expf(sacc[ni][2] - mxB);
            sacc[ni][3] = __expf(sacc[ni][3] - mxB);
            sA += sacc[ni][0] + sacc[ni][1];
            sB += sacc[ni][2] + sacc[ni][3];
        }
        sA += __shfl_xor_sync(0xffffffffu, sA, 1);
        sA += __shfl_xor_sync(0xffffffffu, sA, 2);
        sB += __shfl_xor_sync(0xffffffffu, sB, 1);
        sB += __shfl_xor_sync(0xffffffffu, sB, 2);
        float rA = 1.f / sA, rB = 1.f / sB;

        uint32_t pf[13][4];
        #pragma unroll
        for (int kt = 0; kt < 13; kt++) {
            __half2 h;
            h = __floats2half2_rn(sacc[2*kt][0],   sacc[2*kt][1]);   pf[kt][0] = *(uint32_t*)&h;
            h = __floats2half2_rn(sacc[2*kt][2],   sacc[2*kt][3]);   pf[kt][1] = *(uint32_t*)&h;
            h = __floats2half2_rn(sacc[2*kt+1][0], sacc[2*kt+1][1]); pf[kt][2] = *(uint32_t*)&h;
            h = __floats2half2_rn(sacc[2*kt+1][2], sacc[2*kt+1][3]); pf[kt][3] = *(uint32_t*)&h;
        }

        float oacc[8][4];
        #pragma unroll
        for (int ni = 0; ni < 8; ni++)
            #pragma unroll
            for (int q = 0; q < 4; q++) oacc[ni][q] = 0.f;
        #pragma unroll
        for (int kt = 0; kt < 13; kt++) {
            #pragma unroll
            for (int ng = 0; ng < 4; ng++) {
                uint32_t r[4], bf0[2], bf1[2];
                ldsm4(r, vb + (uint32_t)(ng*16*432) + v_off + kt*32);
                bf0[0] = r[0]; bf0[1] = r[1];
                bf1[0] = r[2]; bf1[1] = r[3];
                mma16816(oacc[2*ng],   pf[kt], bf0);
                mma16816(oacc[2*ng+1], pf[kt], bf1);
            }
        }
        int row0 = rt*16 + lrow, row1 = row0 + 8;
        __half* ob = o + ((size_t)bt*NTOK)*DIMD + hh*DHD;
        #pragma unroll
        for (int ni = 0; ni < 8; ni++) {
            int gc = ni*8 + lcol;
            if (row0 < NTOK) {
                *(__half2*)(ob + (size_t)row0*DIMD + gc) =
                    __floats2half2_rn(oacc[ni][0]*rA, oacc[ni][1]*rA);
            }
            if (row1 < NTOK) {
                *(__half2*)(ob + (size_t)row1*DIMD + gc) =
                    __floats2half2_rn(oacc[ni][2]*rB, oacc[ni][3]*rB);
            }
        }
    }
}

// ---------------- fused weight prep ----------------
#define PREP_BLOCKS 83520
__global__ void prep_weights(const float* __restrict__ conv_w, const float* __restrict__ qkv_w,
                             const float* __restrict__ out_w, const float* __restrict__ ff_w1,
                             const float* __restrict__ ff_w2,
                             __half* __restrict__ wc, __half* __restrict__ wqkv,
                             __half* __restrict__ wo, __half* __restrict__ w1,
                             __half* __restrict__ w2)
{
    __shared__ float tbuf[32][33];
    int b = blockIdx.x;
    int tx = threadIdx.x, ty = threadIdx.y;
    if (b < 576) {
        int r0 = (b/24)*32, c0 = (b%24)*32;
        for (int i = ty; i < 32; i += 8) {
            int idx = (r0+i)*768 + c0 + tx;
            wc[idx] = __float2half(conv_w[idx]);
        }
        return;
    }
    const float* src; __half* dst; int K, N, tl;
    if (b < 21312)      { int t = b-576;   int L=1728; int layer=t/L; tl=t%L; K=768;  N=2304; src=qkv_w+(size_t)layer*K*N; dst=wqkv+(size_t)layer*K*N; }
    else if (b < 28224) { int t = b-21312; int L=576;  int layer=t/L; tl=t%L; K=768;  N=768;  src=out_w+(size_t)layer*K*N; dst=wo  +(size_t)layer*K*N; }
    else if (b < 55872) { int t = b-28224; int L=2304; int layer=t/L; tl=t%L; K=768;  N=3072; src=ff_w1+(size_t)layer*K*N; dst=w1  +(size_t)layer*K*N; }
    else                { int t = b-55872; int L=2304; int layer=t/L; tl=t%L; K=3072; N=768;  src=ff_w2+(size_t)layer*K*N; dst=w2  +(size_t)layer*K*N; }
    int ntn = N / 32;
    int k0 = (tl / ntn) * 32, n0 = (tl % ntn) * 32;
    for (int i = ty; i < 32; i += 8)
        tbuf[i][tx] = src[(size_t)(k0+i)*N + n0 + tx];
    __syncthreads();
    for (int i = ty; i < 32; i += 8)
        dst[(size_t)(n0+i)*K + k0 + tx] = __float2half(tbuf[tx][i]);
}

// ---------------- small kernels ----------------
__global__ void im2col_kernel(const float* __restrict__ img, __half* __restrict__ pv)
{
    int idx = blockIdx.x*256 + threadIdx.x;
    if (idx >= PROWS*DIMD) return;
    int k   = idx % DIMD;
    int row = idx / DIMD;
    int bt = row / NPATCH, p = row % NPATCH;
    int c = k >> 8, rem = k & 255, ii = rem >> 4, jj = rem & 15;
    int ph = p / 14, pw = p % 14;
    pv[idx] = __float2half(img[(((size_t)bt*3 + c)*224 + ph*16 + ii)*224 + pw*16 + jj]);
}

__global__ void clsface_kernel(const float* __restrict__ face, const float* __restrict__ pos,
                               const float* __restrict__ time_emb, const float* __restrict__ cls,
                               float* __restrict__ x)
{
    int idx = blockIdx.x*256 + threadIdx.x;
    if (idx >= BTT*3*DIMD) return;
    int n   = idx % DIMD;
    int rem = idx / DIMD;
    int which = rem % 3;
    int bt  = rem / 3;
    int t   = bt % 20;
    float v; int tok;
    if (which == 0)      { tok = 0;   v = cls[n] + pos[n]; }
    else if (which == 1) { tok = 197; v = face[((size_t)bt*2 + 0)*DIMD + n]; }
    else                 { tok = 198; v = face[((size_t)bt*2 + 1)*DIMD + n]; }
    x[((size_t)bt*NTOK + tok)*DIMD + n] = v + time_emb[t*DIMD + n];
}

// ---------------- output extraction with final FF2 merge ----------------
#define OUT_TOT (3*BTT*DIMD + BTT*NPATCH*DIMD)
__global__ void extract_merge(const float* __restrict__ x, const float* __restrict__ pp,
                              const float* __restrict__ gbias, float* __restrict__ out)
{
    int idx = blockIdx.x*256 + threadIdx.x;
    const int P = BTT*DIMD;
    if (idx >= OUT_TOT) return;
    int bt, tok, n;
    if (idx < 3*P) {
        int part = idx / P;
        int r = idx % P;
        bt = r / DIMD; n = r % DIMD;
        tok = (part == 0) ? 0 : (part == 1 ? 197 : 198);
    } else {
        int r = idx - 3*P;
        n  = r % DIMD;
        tok = 1 + (r / DIMD) % NPATCH;
        bt = r / (DIMD*NPATCH);
    }
    size_t off = ((size_t)bt*NTOK + tok)*DIMD + n;
    out[idx] = x[off] + pp[off] + pp[PPLANE + off] + gbias[n];
}

// ---------------- host ----------------
static void launch_hgemm(int mode, const __half* A, const __half* B, const float* bias,
                         float* C, __half* Ch, int M, int N, int K)
{
    dim3 grid(N/128, (M + 127)/128);
    switch (mode) {
        case 3: hgemm<3><<<grid, 128, GEMM_SMEM>>>(A, B, bias, C, Ch, M, N, K); break;
        case 4: hgemm<4><<<grid, 128, GEMM_SMEM>>>(A, B, bias, C, Ch, M, N, K); break;
    }
}

extern "C" void kernel_launch(void* const* d_in, const int* in_sizes, int n_in,
                              void* d_out, int out_size)
{
    (void)in_sizes; (void)n_in; (void)out_size;
    const float* img      = (const float*)d_in[0];
    const float* face     = (const float*)d_in[1];
    const float* conv_w   = (const float*)d_in[2];
    const float* conv_b   = (const float*)d_in[3];
    const float* pos_emb  = (const float*)d_in[4];
    const float* time_emb = (const float*)d_in[5];
    const float* cls_tok  = (const float*)d_in[6];
    const float* ln1_s    = (const float*)d_in[7];
    const float* ln1_b    = (const float*)d_in[8];
    const float* qkv_w    = (const float*)d_in[9];
    const float* out_w    = (const float*)d_in[10];
    const float* out_b    = (const float*)d_in[11];
    const float* ln2_s    = (const float*)d_in[12];
    const float* ln2_b    = (const float*)d_in[13];
    const float* ff_w1    = (const float*)d_in[14];
    const float* ff_b1    = (const float*)d_in[15];
    const float* ff_w2    = (const float*)d_in[16];
    const float* ff_b2    = (const float*)d_in[17];
    float* out = (float*)d_out;

    float *gx, *gpp;
    __half *gqkvh, *gah, *goh, *gffh, *gwc, *gwqkv, *gwo, *gw1, *gw2;
    cudaGetSymbolAddress((void**)&gx,    g_x);
    cudaGetSymbolAddress((void**)&gpp,   g_pp);
    cudaGetSymbolAddress((void**)&gqkvh, g_qkvh);
    cudaGetSymbolAddress((void**)&gah,   g_ah);
    cudaGetSymbolAddress((void**)&goh,   g_oh);
    cudaGetSymbolAddress((void**)&gffh,  g_ffh);
    cudaGetSymbolAddress((void**)&gwc,   g_wc);
    cudaGetSymbolAddress((void**)&gwqkv, g_wqkv);
    cudaGetSymbolAddress((void**)&gwo,   g_wo);
    cudaGetSymbolAddress((void**)&gw1,   g_w1);
    cudaGetSymbolAddress((void**)&gw2,   g_w2);

    cudaFuncSetAttribute(attn_mma, cudaFuncAttributeMaxDynamicSharedMemorySize, ATTN_SMEM);
    cudaFuncSetAttribute(hgemm<3>, cudaFuncAttributeMaxDynamicSharedMemorySize, GEMM_SMEM);
    cudaFuncSetAttribute(hgemm<4>, cudaFuncAttributeMaxDynamicSharedMemorySize, GEMM_SMEM);
    cudaFuncSetAttribute(hgemm_sk, cudaFuncAttributeMaxDynamicSharedMemorySize, GEMM_SMEM);
    cudaFuncSetAttribute(hgemm_patch, cudaFuncAttributeMaxDynamicSharedMemorySize, GEMM_SMEM);

    prep_weights<<<PREP_BLOCKS, dim3(32,8)>>>(conv_w, qkv_w, out_w, ff_w1, ff_w2,
                                              gwc, gwqkv, gwo, gw1, gw2);
    im2col_kernel<<<(PROWS*DIMD + 255)/256, 256>>>(img, gah);
    clsface_kernel<<<(BTT*3*DIMD + 255)/256, 256>>>(face, pos_emb, time_emb, cls_tok, gx);
    // #4: patch GEMM with fused assemble
    hgemm_patch<<<dim3(DIMD/128, (PROWS+127)/128), 128, GEMM_SMEM>>>(
        gah, gwc, conv_b, pos_emb, time_emb, gx);

    const int LNB = (ROWS + 7)/8;
    for (int l = 0; l < DEPTH; l++) {
        if (l == 0)
            ln_kernel<<<LNB, 256>>>(gx, ln1_s, ln1_b, gah, ROWS);
        else
            ln_merge<<<LNB, 256>>>(gx, gpp, ff_b2 + (l-1)*DIMD,
                                   ln1_s + l*DIMD, ln1_b + l*DIMD, gah, ROWS);
        launch_hgemm(4, gah, gwqkv + (size_t)l*3*DIMD*DIMD, nullptr,
                     nullptr, gqkvh, ROWS, 3*DIMD, DIMD);
        attn_mma<<<BTT*HEADS, 128, ATTN_SMEM>>>(gqkvh, goh);
        hgemm_sk<<<dim3(DIMD/128, (ROWS+127)/128, 2), 128, GEMM_SMEM>>>(
            goh, gwo + (size_t)l*DIMD*DIMD, gpp, ROWS, DIMD, DIMD, DIMD/2);
        ln_merge<<<LNB, 256>>>(gx, gpp, out_b + l*DIMD,
                               ln2_s + l*DIMD, ln2_b + l*DIMD, gah, ROWS);
        launch_hgemm(3, gah, gw1 + (size_t)l*MLPD*DIMD, ff_b1 + l*MLPD,
                     nullptr, gffh, ROWS, MLPD, DIMD);
        hgemm_sk<<<dim3(DIMD/128, (ROWS+127)/128, 2), 128, GEMM_SMEM>>>(
            gffh, gw2 + (size_t)l*DIMD*MLPD, gpp, ROWS, DIMD, MLPD, MLPD/2);
    }

    extract_merge<<<(OUT_TOT + 255)/256, 256>>>(gx, gpp, ff_b2 + 11*DIMD, out);
}